// round 14
// baseline (speedup 1.0000x reference)
#include <cuda_runtime.h>
#include <cuda_bf16.h>
#include <math.h>
#include <stdint.h>

#define D 128
#define MAXN 100000
#define MAXE 300000
#define BN_EPS 1e-5f
#define EPW 8   // edges per warp in scatter

// ---------------- device scratch (static; no cudaMalloc allowed) -------------
__device__ __align__(16) float g_agg[3 * MAXN * D];      // per-type neighbor sums
__device__ __align__(16) float g_cnt[3 * MAXN + 4];      // per-type in-degree
__device__ __align__(16) float g_comb[MAXN * D];         // comb (raw, pre-BN)
__device__ __align__(16) float g_aggY[MAXN * D];         // final-layer neighbor sums (BN'd)
__device__ __align__(16) float g_stats[256];             // [sum(128) | sumsq(128)]
__device__ __align__(16) float g_b1[128];
__device__ __align__(16) float g_bnS[128];               // BN scale
__device__ __align__(16) float g_bnB[128];               // BN shift
__device__ __align__(16) __nv_bfloat16 g_W1h[128 * 640];
__device__ __align__(16) __nv_bfloat16 g_W1l[128 * 640];
__device__ __align__(16) __nv_bfloat16 g_W2h[128 * 256];
__device__ __align__(16) __nv_bfloat16 g_W2l[128 * 256];

// ---------------- zero scratch each call --------------------------------------
__global__ void zero_bufs() {
    size_t idx = (size_t)blockIdx.x * blockDim.x + threadIdx.x;
    float4 z = make_float4(0.f, 0.f, 0.f, 0.f);
    const size_t A4 = (size_t)3 * MAXN * (D / 4);
    const size_t Y4 = (size_t)MAXN * (D / 4);
    const size_t C4 = (3 * MAXN) / 4;
    if (idx < A4) { ((float4*)g_agg)[idx] = z; return; }
    idx -= A4;
    if (idx < Y4) { ((float4*)g_aggY)[idx] = z; return; }
    idx -= Y4;
    if (idx < C4) { ((float4*)g_cnt)[idx] = z; return; }
    idx -= C4;
    if (idx < 64) ((float4*)g_stats)[idx] = z;
}

// ---------------- merged 3-type scatter, 8 edges per warp ---------------------
template<int PHASE>
__global__ void scatter3(const float4* __restrict__ x,
                         const int* __restrict__ s0, const int* __restrict__ d0,
                         const int* __restrict__ s1, const int* __restrict__ d1,
                         const int* __restrict__ s2, const int* __restrict__ d2,
                         int n0, int n1, int n2, int bPer) {
    int type = blockIdx.x / bPer;
    int rem  = blockIdx.x - type * bPer;
    int w    = rem * (blockDim.x >> 5) + (threadIdx.x >> 5);
    int lane = threadIdx.x & 31;

    const int* src; const int* dst; int nE;
    if (type == 0)      { src = s0; dst = d0; nE = n0; }
    else if (type == 1) { src = s1; dst = d1; nE = n1; }
    else                { src = s2; dst = d2; nE = n2; }

    int e0 = w * EPW;
    if (e0 >= nE) return;

    const float4* xv = (PHASE == 0) ? x : (const float4*)g_comb;
    float* agg;
    float4 S, B;
    if (PHASE == 0) {
        agg = g_agg + (size_t)type * MAXN * D;
    } else {
        agg = g_aggY;
        S = ((const float4*)g_bnS)[lane];
        B = ((const float4*)g_bnB)[lane];
    }

    int se[EPW], de[EPW];
    #pragma unroll
    for (int i = 0; i < EPW; i++) {
        int e = e0 + i;
        if (e < nE) { se[i] = __ldg(src + e); de[i] = __ldg(dst + e); }
        else se[i] = -1;
    }
    float4 v[EPW];
    #pragma unroll
    for (int i = 0; i < EPW; i++)
        if (se[i] >= 0) v[i] = xv[(size_t)se[i] * 32 + lane];

    if (PHASE == 1) {
        #pragma unroll
        for (int i = 0; i < EPW; i++) {
            if (se[i] >= 0) {
                v[i].x = v[i].x * S.x + B.x;
                v[i].y = v[i].y * S.y + B.y;
                v[i].z = v[i].z * S.z + B.z;
                v[i].w = v[i].w * S.w + B.w;
            }
        }
    }
    #pragma unroll
    for (int i = 0; i < EPW; i++) {
        if (se[i] >= 0) {
            float* p = agg + (size_t)de[i] * D + lane * 4;
            asm volatile("red.global.add.v4.f32 [%0], {%1,%2,%3,%4};"
                         :: "l"(p), "f"(v[i].x), "f"(v[i].y), "f"(v[i].z), "f"(v[i].w)
                         : "memory");
        }
    }
    if (PHASE == 0 && lane < EPW) {
        int e = e0 + lane;
        if (e < nE) atomicAdd(g_cnt + (size_t)type * MAXN + __ldg(dst + e), 1.0f);
    }
}

// ---------------- fold weights + bf16 hi/lo split ------------------------------
__global__ void prep_weights(const float* __restrict__ Wl0, const float* __restrict__ Wr0,
                             const float* __restrict__ Wl1, const float* __restrict__ Wr1,
                             const float* __restrict__ Wl2, const float* __restrict__ Wr2,
                             const float* __restrict__ Wla, const float* __restrict__ Wra,
                             const float* __restrict__ Wf,  const float* __restrict__ Wrf,
                             const float* __restrict__ bl0, const float* __restrict__ bl1,
                             const float* __restrict__ bl2, const float* __restrict__ bla,
                             const float* __restrict__ wt) {
    int idx = blockIdx.x * blockDim.x + threadIdx.x;
    float w0 = wt[0], w1 = wt[1], w2 = wt[2];
    if (idx < 128 * 640) {
        int j = idx / 640, k = idx - j * 640;
        int seg = k >> 7, kk = k & 127;
        float v;
        if (seg == 0)      v = w0 * Wl0[j * 128 + kk];
        else if (seg == 1) v = w1 * Wl1[j * 128 + kk];
        else if (seg == 2) v = w2 * Wl2[j * 128 + kk];
        else if (seg == 3) v = Wla[j * 128 + kk];
        else v = w0 * Wr0[j * 128 + kk] + w1 * Wr1[j * 128 + kk]
               + w2 * Wr2[j * 128 + kk] + Wra[j * 128 + kk];
        __nv_bfloat16 h = __float2bfloat16_rn(v);
        g_W1h[idx] = h;
        g_W1l[idx] = __float2bfloat16_rn(v - __bfloat162float(h));
    }
    if (idx < 128 * 256) {
        int j = idx >> 8, k = idx & 255;
        float v = (k < 128) ? Wf[j * 128 + k] : Wrf[j * 128 + (k - 128)];
        __nv_bfloat16 h = __float2bfloat16_rn(v);
        g_W2h[idx] = h;
        g_W2l[idx] = __float2bfloat16_rn(v - __bfloat162float(h));
    }
    if (idx < 128)
        g_b1[idx] = w0 * bl0[idx] + w1 * bl1[idx] + w2 * bl2[idx] + bla[idx];
}

// ---------------- BN finalize: stats -> scale/shift ----------------------------
__global__ void bn_finalize(const float* __restrict__ gamma,
                            const float* __restrict__ beta, int n) {
    int j = threadIdx.x;
    float invN = 1.0f / (float)n;
    float mu  = g_stats[j] * invN;
    float var = g_stats[128 + j] * invN - mu * mu;
    float s = rsqrtf(var + BN_EPS) * gamma[j];
    g_bnS[j] = s;
    g_bnB[j] = beta[j] - mu * s;
}

// ---------------- HMMA helper -------------------------------------------------
__device__ __forceinline__ void mma16816(float* c, const uint32_t* a, const uint32_t* b) {
    asm volatile(
        "mma.sync.aligned.m16n8k16.row.col.f32.bf16.bf16.f32 "
        "{%0,%1,%2,%3}, {%4,%5,%6,%7}, {%8,%9}, {%0,%1,%2,%3};"
        : "+f"(c[0]), "+f"(c[1]), "+f"(c[2]), "+f"(c[3])
        : "r"(a[0]), "r"(a[1]), "r"(a[2]), "r"(a[3]), "r"(b[0]), "r"(b[1]));
}

// Cheap fp32 -> bf16 hi/lo pair split
__device__ __forceinline__ void split_pair(float x0, float x1,
                                           uint32_t& hw, uint32_t& lw) {
    uint32_t f0 = __float_as_uint(x0);
    uint32_t f1 = __float_as_uint(x1);
    hw = __byte_perm(f0, f1, 0x7632);
    float l0 = x0 - __uint_as_float(f0 & 0xffff0000u);
    float l1 = x1 - __uint_as_float(f1 & 0xffff0000u);
    asm("cvt.rn.bf16x2.f32 %0, %1, %2;" : "=r"(lw) : "f"(l1), "f"(l0));
}

// ---------------- tensor-core GEMM: C[M,128] = A[M,K] @ W[128,K]^T + bias -----
#define PITCH 72
#define TILE_B (128 * PITCH * 2)   // bytes per bf16 tile (18432)
#define SUMBUF_B (128 * 64 * 4)    // 32KB fp32 running-sum scratch (GEMM1 only)

template<int K, bool FIRST>
__global__ __launch_bounds__(256, 2)
void gemm_hmma(const float* __restrict__ feat, const float* __restrict__ bias_ext,
               float* __restrict__ Cext, int M) {
    constexpr int NC = K / 64;

    extern __shared__ char dyn[];
    __shared__ float sInv[128][4];
    __shared__ float sBias[128];

    char* Ah = dyn;
    char* Al = dyn + TILE_B;
    char* Bh = dyn + 2 * TILE_B;
    char* Bl = dyn + 3 * TILE_B;
    float* sumBuf = (float*)(dyn + 4 * TILE_B);   // FIRST only
    uint32_t* Ah32 = (uint32_t*)Ah;
    uint32_t* Al32 = (uint32_t*)Al;
    uint32_t* Bh32 = (uint32_t*)Bh;
    uint32_t* Bl32 = (uint32_t*)Bl;
    uint32_t BhS = (uint32_t)__cvta_generic_to_shared(Bh);
    uint32_t BlS = (uint32_t)__cvta_generic_to_shared(Bl);

    int t = threadIdx.x;
    int row0 = blockIdx.x * 128;
    int lane = t & 31;
    int wid = t >> 5;
    int g = lane >> 2, tig = lane & 3;
    int warpM = wid >> 2;      // 0..1 -> 64-row slab
    int warpN = wid & 3;       // 0..3 -> 32-col slab

    if (t < 128) {
        int node = row0 + t;
        float i0 = 0.f, i1 = 0.f, i2 = 0.f, ia = 0.f;
        if (node < M) {
            float c0 = g_cnt[node], c1 = g_cnt[MAXN + node], c2 = g_cnt[2 * MAXN + node];
            i0 = 1.f / fmaxf(c0, 1.f);
            i1 = 1.f / fmaxf(c1, 1.f);
            i2 = 1.f / fmaxf(c2, 1.f);
            ia = 1.f / fmaxf(c0 + c1 + c2, 1.f);
        }
        sInv[t][0] = i0; sInv[t][1] = i1; sInv[t][2] = i2; sInv[t][3] = ia;
        sBias[t] = FIRST ? g_b1[t] : bias_ext[t];
    }

    const __nv_bfloat16* WH = FIRST ? g_W1h : g_W2h;
    const __nv_bfloat16* WL = FIRST ? g_W1l : g_W2l;

    float acc[4][4][4];
    #pragma unroll
    for (int i = 0; i < 4; i++)
        #pragma unroll
        for (int j = 0; j < 4; j++)
            #pragma unroll
            for (int q = 0; q < 4; q++) acc[i][j][q] = 0.f;

    __syncthreads();  // sInv/sBias visible

    // Chunk order: half-0 of segs 0-2, then seg3-half-0 (from sumBuf), then
    // half-1 of segs 0-2, seg3-half-1, then feat. K-sum is order-independent.
    const int ord10[10] = {0, 2, 4, 6, 1, 3, 5, 7, 8, 9};

    for (int ci = 0; ci < NC; ci++) {
        int c = FIRST ? ord10[ci] : ci;

        // --- B tile fill via cp.async -----------------------------------
        #pragma unroll
        for (int i = 0; i < 4; i++) {
            int u = t + i * 256;
            int nrow = u >> 3, kk8 = (u & 7) * 8;
            size_t gidx = (size_t)nrow * K + c * 64 + kk8;
            uint32_t so = (uint32_t)(nrow * PITCH + kk8) * 2;
            asm volatile("cp.async.cg.shared.global [%0], [%1], 16;"
                         :: "r"(BhS + so), "l"(WH + gidx));
            asm volatile("cp.async.cg.shared.global [%0], [%1], 16;"
                         :: "r"(BlS + so), "l"(WL + gidx));
        }
        asm volatile("cp.async.commit_group;");

        // --- A tile fill -------------------------------------------------
        #pragma unroll
        for (int i = 0; i < 4; i++) {
            int u = t + i * 256;
            int m = u >> 3, kk8 = (u & 7) * 8;
            int node = row0 + m;
            float v[8];
            #pragma unroll
            for (int j = 0; j < 8; j++) v[j] = 0.f;
            if (node < M) {
                if (FIRST) {
                    if (c < 6) {                 // segs 0-2
                        int seg = c >> 1;
                        int kk = ((c & 1) << 6) + kk8;
                        const float4* p = (const float4*)(g_agg + ((size_t)seg * MAXN + node) * 128 + kk);
                        float4 a = p[0], b = p[1];
                        float sc = sInv[m][seg];
                        float* sb = sumBuf + m * 64 + kk8;
                        if (c < 2) {             // first chunk of this half: init
                            *(float4*)(sb)     = a;
                            *(float4*)(sb + 4) = b;
                        } else {                 // accumulate raw sums
                            float4 s0 = *(float4*)(sb);
                            float4 s1 = *(float4*)(sb + 4);
                            s0.x += a.x; s0.y += a.y; s0.z += a.z; s0.w += a.w;
                            s1.x += b.x; s1.y += b.y; s1.z += b.z; s1.w += b.w;
                            *(float4*)(sb)     = s0;
                            *(float4*)(sb + 4) = s1;
                        }
                        v[0] = a.x * sc; v[1] = a.y * sc; v[2] = a.z * sc; v[3] = a.w * sc;
                        v[4] = b.x * sc; v[5] = b.y * sc; v[6] = b.z * sc; v[7] = b.w * sc;
                    } else if (c < 8) {          // seg3: consume running sums
                        float sc = sInv[m][3];
                        const float* sb = sumBuf + m * 64 + kk8;
                        float4 s0 = *(const float4*)(sb);
                        float4 s1 = *(const float4*)(sb + 4);
                        v[0] = s0.x * sc; v[1] = s0.y * sc; v[2] = s0.z * sc; v[3] = s0.w * sc;
                        v[4] = s1.x * sc; v[5] = s1.y * sc; v[6] = s1.z * sc; v[7] = s1.w * sc;
                    } else {                     // feat
                        int kk = ((c & 1) << 6) + kk8;
                        const float4* p = (const float4*)(feat + (size_t)node * 128 + kk);
                        float4 a = p[0], b = p[1];
                        v[0] = a.x; v[1] = a.y; v[2] = a.z; v[3] = a.w;
                        v[4] = b.x; v[5] = b.y; v[6] = b.z; v[7] = b.w;
                    }
                } else {
                    int k0 = c * 64 + kk8;
                    int seg = k0 >> 7, kk = k0 & 127;
                    if (seg == 0) {
                        float sc = sInv[m][3];
                        const float4* p = (const float4*)(g_aggY + (size_t)node * 128 + kk);
                        float4 a = p[0], b = p[1];
                        v[0] = a.x * sc; v[1] = a.y * sc; v[2] = a.z * sc; v[3] = a.w * sc;
                        v[4] = b.x * sc; v[5] = b.y * sc; v[6] = b.z * sc; v[7] = b.w * sc;
                    } else {
                        const float4* p = (const float4*)(g_comb + (size_t)node * 128 + kk);
                        float4 a = p[0], b = p[1];
                        float4 S0 = *(const float4*)(g_bnS + kk);
                        float4 S1 = *(const float4*)(g_bnS + kk + 4);
                        float4 B0 = *(const float4*)(g_bnB + kk);
                        float4 B1 = *(const float4*)(g_bnB + kk + 4);
                        v[0] = a.x * S0.x + B0.x; v[1] = a.y * S0.y + B0.y;
                        v[2] = a.z * S0.z + B0.z; v[3] = a.w * S0.w + B0.w;
                        v[4] = b.x * S1.x + B1.x; v[5] = b.y * S1.y + B1.y;
                        v[6] = b.z * S1.z + B1.z; v[7] = b.w * S1.w + B1.w;
                    }
                }
            }
            uint32_t hw[4], lw[4];
            #pragma unroll
            for (int p2 = 0; p2 < 4; p2++)
                split_pair(v[2 * p2], v[2 * p2 + 1], hw[p2], lw[p2]);
            int so = m * PITCH + kk8;
            *(uint4*)(Ah + so * 2) = make_uint4(hw[0], hw[1], hw[2], hw[3]);
            *(uint4*)(Al + so * 2) = make_uint4(lw[0], lw[1], lw[2], lw[3]);
        }
        asm volatile("cp.async.wait_group 0;" ::: "memory");
        __syncthreads();

        // --- compute: warp (warpM, warpN) owns 64x32 of the 128x128 tile ----
        #pragma unroll
        for (int ks = 0; ks < 4; ks++) {
            int kw = (ks * 16 + 2 * tig) >> 1;
            uint32_t bh[4][2], bl[4][2];
            #pragma unroll
            for (int nA = 0; nA < 4; nA++) {
                int cN = warpN * 32 + nA * 8 + g;
                bh[nA][0] = Bh32[cN * 36 + kw];
                bh[nA][1] = Bh32[cN * 36 + kw + 4];
                bl[nA][0] = Bl32[cN * 36 + kw];
                bl[nA][1] = Bl32[cN * 36 + kw + 4];
            }
            #pragma unroll
            for (int mA = 0; mA < 4; mA++) {
                int r0 = warpM * 64 + mA * 16 + g;
                uint32_t ah[4], al[4];
                ah[0] = Ah32[r0 * 36 + kw];
                ah[1] = Ah32[(r0 + 8) * 36 + kw];
                ah[2] = Ah32[r0 * 36 + kw + 4];
                ah[3] = Ah32[(r0 + 8) * 36 + kw + 4];
                al[0] = Al32[r0 * 36 + kw];
                al[1] = Al32[(r0 + 8) * 36 + kw];
                al[2] = Al32[r0 * 36 + kw + 4];
                al[3] = Al32[(r0 + 8) * 36 + kw + 4];
                #pragma unroll
                for (int nA = 0; nA < 4; nA++) {
                    mma16816(acc[mA][nA], ah, bh[nA]);
                    mma16816(acc[mA][nA], ah, bl[nA]);
                    mma16816(acc[mA][nA], al, bh[nA]);
                }
            }
        }
        __syncthreads();
    }

    // --- epilogue: bias (+ReLU), stores; FIRST also accumulates BN stats ----
    float* Cp = FIRST ? g_comb : Cext;
    float* sS = (float*)dyn;            // reuse tile smem (synced above)
    float* sQ = sS + 128;
    if (FIRST) {
        if (t < 128) { sS[t] = 0.f; sQ[t] = 0.f; }
        __syncthreads();
    }

    #pragma unroll
    for (int nA = 0; nA < 4; nA++) {
        int col = warpN * 32 + nA * 8 + 2 * tig;
        float s0 = 0.f, s1 = 0.f, q0 = 0.f, q1 = 0.f;
        #pragma unroll
        for (int mA = 0; mA < 4; mA++) {
            #pragma unroll
            for (int half = 0; half < 2; half++) {
                int row = row0 + warpM * 64 + mA * 16 + g + half * 8;
                if (row < M) {
                    float v0 = acc[mA][nA][half * 2 + 0] + sBias[col];
                    float v1 = acc[mA][nA][half * 2 + 1] + sBias[col + 1];
                    if (FIRST) { v0 = fmaxf(v0, 0.f); v1 = fmaxf(v1, 0.f); }
                    *(float2*)&Cp[(size_t)row * 128 + col] = make_float2(v0, v1);
                    if (FIRST) {
                        s0 += v0; s1 += v1;
                        q0 += v0 * v0; q1 += v1 * v1;
                    }
                }
            }
        }
        if (FIRST) {
            atomicAdd(&sS[col], s0); atomicAdd(&sS[col + 1], s1);
            atomicAdd(&sQ[col], q0); atomicAdd(&sQ[col + 1], q1);
        }
    }
    if (FIRST) {
        __syncthreads();
        if (t < 128) {
            atomicAdd(&g_stats[t], sS[t]);
            atomicAdd(&g_stats[128 + t], sQ[t]);
        }
    }
}

// ---------------- host launcher ----------------------------------------------
extern "C" void kernel_launch(void* const* d_in, const int* in_sizes, int n_in,
                              void* d_out, int out_size) {
    const float* feat = nullptr;
    const int* ei[3] = {nullptr, nullptr, nullptr};
    int ne[3] = {0, 0, 0};
    const float* Wm[10] = {};
    const float* vec[7] = {};
    const float* wt = nullptr;
    int ke = 0, km = 0, kv = 0, n = 0;

    for (int i = 0; i < n_in; i++) {
        int sz = in_sizes[i];
        if (sz == 3) { wt = (const float*)d_in[i]; }
        else if (sz == D) { if (kv < 7) vec[kv++] = (const float*)d_in[i]; }
        else if (sz == D * D) { if (km < 10) Wm[km++] = (const float*)d_in[i]; }
        else if (sz == 2 * MAXE) { if (ke < 3) { ei[ke] = (const int*)d_in[i]; ne[ke] = sz / 2; ke++; } }
        else if (sz == MAXN * D) { feat = (const float*)d_in[i]; n = sz / D; }
    }
    if (!feat || ke != 3 || km != 10 || kv != 7 || !wt) return;

    const float* Wl0 = Wm[0], *Wr0 = Wm[1], *Wl1 = Wm[2], *Wr1 = Wm[3];
    const float* Wl2 = Wm[4], *Wr2 = Wm[5], *Wla = Wm[6], *Wra = Wm[7];
    const float* Wf  = Wm[8], *Wrf = Wm[9];
    const float* bl0 = vec[0], *bl1 = vec[1], *bl2 = vec[2], *bla = vec[3];
    const float* bf  = vec[4], *gamma = vec[5], *beta = vec[6];

    const int T = 256;
    const int SMEM1 = 4 * TILE_B + SUMBUF_B;  // 106496 bytes (GEMM1)
    const int SMEM2 = 4 * TILE_B;             // 73728 bytes (GEMM2)
    cudaFuncSetAttribute(gemm_hmma<640, true>,
                         cudaFuncAttributeMaxDynamicSharedMemorySize, SMEM1);
    cudaFuncSetAttribute(gemm_hmma<256, false>,
                         cudaFuncAttributeMaxDynamicSharedMemorySize, SMEM2);

    int neMax = ne[0] > ne[1] ? ne[0] : ne[1];
    if (ne[2] > neMax) neMax = ne[2];
    int edgesPerBlock = (T / 32) * EPW;   // 64
    int bPer = (neMax + edgesPerBlock - 1) / edgesPerBlock;

    // 1) zero scratch
    {
        size_t tot = (size_t)3 * MAXN * 32 + (size_t)MAXN * 32 + (3 * MAXN) / 4 + 64;
        zero_bufs<<<(unsigned)((tot + T - 1) / T), T>>>();
    }
    // 2) phase-1 scatter (all 3 types in one launch)
    scatter3<0><<<3 * bPer, T>>>((const float4*)feat,
                                 ei[0], ei[0] + ne[0], ei[1], ei[1] + ne[1],
                                 ei[2], ei[2] + ne[2], ne[0], ne[1], ne[2], bPer);
    // 3) fold weights + bf16 split
    prep_weights<<<(128 * 640 + T - 1) / T, T>>>(Wl0, Wr0, Wl1, Wr1, Wl2, Wr2,
                                                 Wla, Wra, Wf, Wrf,
                                                 bl0, bl1, bl2, bla, wt);
    // 4) GEMM1 (HMMA bf16x3, fused mean + bias + relu + BN-stats) -> g_comb
    {
        int blocks = (n + 127) / 128;
        gemm_hmma<640, true><<<blocks, 256, SMEM1>>>(feat, nullptr, nullptr, n);
    }
    // 5) BN finalize (scale/shift)
    bn_finalize<<<1, 128>>>(gamma, beta, n);
    // 6) phase-2 scatter (source = g_comb selected device-side, BN on read)
    scatter3<1><<<3 * bPer, T>>>((const float4*)feat,
                                 ei[0], ei[0] + ne[0], ei[1], ei[1] + ne[1],
                                 ei[2], ei[2] + ne[2], ne[0], ne[1], ne[2], bPer);
    // 7) GEMM2 (HMMA bf16x3, fused mean + BN + bias) -> d_out
    {
        int blocks = (n + 127) / 128;
        gemm_hmma<256, false><<<blocks, 256, SMEM2>>>(feat, bf, (float*)d_out, n);
    }
    (void)out_size;
}

// round 15
// speedup vs baseline: 1.0230x; 1.0230x over previous
#include <cuda_runtime.h>
#include <cuda_bf16.h>
#include <math.h>
#include <stdint.h>

#define D 128
#define MAXN 100000
#define MAXE 300000
#define BN_EPS 1e-5f
#define EPW 8   // edges per warp in scatter

// ---------------- device scratch (static; no cudaMalloc allowed) -------------
__device__ __align__(16) float g_agg[3 * MAXN * D];      // per-type neighbor sums
__device__ __align__(16) float g_cnt[3 * MAXN + 4];      // per-type in-degree
__device__ __align__(16) float g_comb[MAXN * D];         // comb (raw, pre-BN)
__device__ __align__(16) float g_aggY[MAXN * D];         // final-layer neighbor sums (BN'd)
__device__ __align__(16) float g_stats[256];             // [sum(128) | sumsq(128)]
__device__ __align__(16) float g_b1[128];
__device__ __align__(16) float g_bnS[128];               // BN scale
__device__ __align__(16) float g_bnB[128];               // BN shift
__device__ __align__(16) __nv_bfloat16 g_W1h[128 * 640];
__device__ __align__(16) __nv_bfloat16 g_W1l[128 * 640];
__device__ __align__(16) __nv_bfloat16 g_W2h[128 * 256];
__device__ __align__(16) __nv_bfloat16 g_W2l[128 * 256];

// ---------------- zero scratch each call --------------------------------------
__global__ void zero_bufs() {
    size_t idx = (size_t)blockIdx.x * blockDim.x + threadIdx.x;
    float4 z = make_float4(0.f, 0.f, 0.f, 0.f);
    const size_t A4 = (size_t)3 * MAXN * (D / 4);
    const size_t Y4 = (size_t)MAXN * (D / 4);
    const size_t C4 = (3 * MAXN) / 4;
    if (idx < A4) { ((float4*)g_agg)[idx] = z; return; }
    idx -= A4;
    if (idx < Y4) { ((float4*)g_aggY)[idx] = z; return; }
    idx -= Y4;
    if (idx < C4) { ((float4*)g_cnt)[idx] = z; return; }
    idx -= C4;
    if (idx < 64) ((float4*)g_stats)[idx] = z;
}

// ---------------- merged 3-type scatter, 8 edges per warp ---------------------
template<int PHASE>
__global__ void scatter3(const float4* __restrict__ x,
                         const int* __restrict__ s0, const int* __restrict__ d0,
                         const int* __restrict__ s1, const int* __restrict__ d1,
                         const int* __restrict__ s2, const int* __restrict__ d2,
                         int n0, int n1, int n2, int bPer) {
    int type = blockIdx.x / bPer;
    int rem  = blockIdx.x - type * bPer;
    int w    = rem * (blockDim.x >> 5) + (threadIdx.x >> 5);
    int lane = threadIdx.x & 31;

    const int* src; const int* dst; int nE;
    if (type == 0)      { src = s0; dst = d0; nE = n0; }
    else if (type == 1) { src = s1; dst = d1; nE = n1; }
    else                { src = s2; dst = d2; nE = n2; }

    int e0 = w * EPW;
    if (e0 >= nE) return;

    const float4* xv = (PHASE == 0) ? x : (const float4*)g_comb;
    float* agg;
    float4 S, B;
    if (PHASE == 0) {
        agg = g_agg + (size_t)type * MAXN * D;
    } else {
        agg = g_aggY;
        S = ((const float4*)g_bnS)[lane];
        B = ((const float4*)g_bnB)[lane];
    }

    int se[EPW], de[EPW];
    #pragma unroll
    for (int i = 0; i < EPW; i++) {
        int e = e0 + i;
        if (e < nE) { se[i] = __ldg(src + e); de[i] = __ldg(dst + e); }
        else se[i] = -1;
    }
    float4 v[EPW];
    #pragma unroll
    for (int i = 0; i < EPW; i++)
        if (se[i] >= 0) v[i] = xv[(size_t)se[i] * 32 + lane];

    if (PHASE == 1) {
        #pragma unroll
        for (int i = 0; i < EPW; i++) {
            if (se[i] >= 0) {
                v[i].x = v[i].x * S.x + B.x;
                v[i].y = v[i].y * S.y + B.y;
                v[i].z = v[i].z * S.z + B.z;
                v[i].w = v[i].w * S.w + B.w;
            }
        }
    }
    #pragma unroll
    for (int i = 0; i < EPW; i++) {
        if (se[i] >= 0) {
            float* p = agg + (size_t)de[i] * D + lane * 4;
            asm volatile("red.global.add.v4.f32 [%0], {%1,%2,%3,%4};"
                         :: "l"(p), "f"(v[i].x), "f"(v[i].y), "f"(v[i].z), "f"(v[i].w)
                         : "memory");
        }
    }
    if (PHASE == 0 && lane < EPW) {
        int e = e0 + lane;
        if (e < nE) atomicAdd(g_cnt + (size_t)type * MAXN + __ldg(dst + e), 1.0f);
    }
}

// ---------------- fold weights + bf16 hi/lo split ------------------------------
__global__ void prep_weights(const float* __restrict__ Wl0, const float* __restrict__ Wr0,
                             const float* __restrict__ Wl1, const float* __restrict__ Wr1,
                             const float* __restrict__ Wl2, const float* __restrict__ Wr2,
                             const float* __restrict__ Wla, const float* __restrict__ Wra,
                             const float* __restrict__ Wf,  const float* __restrict__ Wrf,
                             const float* __restrict__ bl0, const float* __restrict__ bl1,
                             const float* __restrict__ bl2, const float* __restrict__ bla,
                             const float* __restrict__ wt) {
    int idx = blockIdx.x * blockDim.x + threadIdx.x;
    float w0 = wt[0], w1 = wt[1], w2 = wt[2];
    if (idx < 128 * 640) {
        int j = idx / 640, k = idx - j * 640;
        int seg = k >> 7, kk = k & 127;
        float v;
        if (seg == 0)      v = w0 * Wl0[j * 128 + kk];
        else if (seg == 1) v = w1 * Wl1[j * 128 + kk];
        else if (seg == 2) v = w2 * Wl2[j * 128 + kk];
        else if (seg == 3) v = Wla[j * 128 + kk];
        else v = w0 * Wr0[j * 128 + kk] + w1 * Wr1[j * 128 + kk]
               + w2 * Wr2[j * 128 + kk] + Wra[j * 128 + kk];
        __nv_bfloat16 h = __float2bfloat16_rn(v);
        g_W1h[idx] = h;
        g_W1l[idx] = __float2bfloat16_rn(v - __bfloat162float(h));
    }
    if (idx < 128 * 256) {
        int j = idx >> 8, k = idx & 255;
        float v = (k < 128) ? Wf[j * 128 + k] : Wrf[j * 128 + (k - 128)];
        __nv_bfloat16 h = __float2bfloat16_rn(v);
        g_W2h[idx] = h;
        g_W2l[idx] = __float2bfloat16_rn(v - __bfloat162float(h));
    }
    if (idx < 128)
        g_b1[idx] = w0 * bl0[idx] + w1 * bl1[idx] + w2 * bl2[idx] + bla[idx];
}

// ---------------- BN finalize: stats -> scale/shift ----------------------------
__global__ void bn_finalize(const float* __restrict__ gamma,
                            const float* __restrict__ beta, int n) {
    int j = threadIdx.x;
    float invN = 1.0f / (float)n;
    float mu  = g_stats[j] * invN;
    float var = g_stats[128 + j] * invN - mu * mu;
    float s = rsqrtf(var + BN_EPS) * gamma[j];
    g_bnS[j] = s;
    g_bnB[j] = beta[j] - mu * s;
}

// ---------------- HMMA helper -------------------------------------------------
__device__ __forceinline__ void mma16816(float* c, const uint32_t* a, const uint32_t* b) {
    asm volatile(
        "mma.sync.aligned.m16n8k16.row.col.f32.bf16.bf16.f32 "
        "{%0,%1,%2,%3}, {%4,%5,%6,%7}, {%8,%9}, {%0,%1,%2,%3};"
        : "+f"(c[0]), "+f"(c[1]), "+f"(c[2]), "+f"(c[3])
        : "r"(a[0]), "r"(a[1]), "r"(a[2]), "r"(a[3]), "r"(b[0]), "r"(b[1]));
}

// Cheap fp32 -> bf16 hi/lo pair split
__device__ __forceinline__ void split_pair(float x0, float x1,
                                           uint32_t& hw, uint32_t& lw) {
    uint32_t f0 = __float_as_uint(x0);
    uint32_t f1 = __float_as_uint(x1);
    hw = __byte_perm(f0, f1, 0x7632);
    float l0 = x0 - __uint_as_float(f0 & 0xffff0000u);
    float l1 = x1 - __uint_as_float(f1 & 0xffff0000u);
    asm("cvt.rn.bf16x2.f32 %0, %1, %2;" : "=r"(lw) : "f"(l1), "f"(l0));
}

// ---------------- pipelined tensor-core GEMM ----------------------------------
// C[M,128] = A[M,K] @ W[128,K]^T + bias, bf16x3, 32-wide K chunks,
// cp.async double-buffered staging for A (raw fp32) and B (bf16).
#define AP_W 20          // A/B tile pitch in 32-bit words (40 bf16 elems, 80B)
#define TILE_BYTES 10240 // 128 rows * 80B
#define ST_PITCH 36      // stage pitch in floats (144B)
#define ST_BYTES 18432   // 128 * 144
#define OFF_AH 0
#define OFF_AL 10240
#define OFF_B  20480     // + buf*20480: Bh ; +10240: Bl
#define OFF_ST 61440     // + buf*18432
#define SMEM_TOT 98304

template<int K, bool FIRST>
__global__ __launch_bounds__(256, 2)
void gemm_hmma(const float* __restrict__ feat, const float* __restrict__ bias_ext,
               float* __restrict__ Cext, int M) {
    constexpr int NC = K / 32;

    extern __shared__ char dyn[];
    __shared__ float sInv[128][4];
    __shared__ float sBias[128];

    uint32_t dynS = (uint32_t)__cvta_generic_to_shared(dyn);
    uint32_t* Ah32 = (uint32_t*)(dyn + OFF_AH);
    uint32_t* Al32 = (uint32_t*)(dyn + OFF_AL);

    int t = threadIdx.x;
    int row0 = blockIdx.x * 128;
    int lane = t & 31;
    int wid = t >> 5;
    int g = lane >> 2, tig = lane & 3;
    int warpM = wid >> 2;      // 0..1 -> 64-row slab
    int warpN = wid & 3;       // 0..3 -> 32-col slab

    if (t < 128) {
        int node = row0 + t;
        float i0 = 0.f, i1 = 0.f, i2 = 0.f, ia = 0.f;
        if (node < M) {
            float c0 = g_cnt[node], c1 = g_cnt[MAXN + node], c2 = g_cnt[2 * MAXN + node];
            i0 = 1.f / fmaxf(c0, 1.f);
            i1 = 1.f / fmaxf(c1, 1.f);
            i2 = 1.f / fmaxf(c2, 1.f);
            ia = 1.f / fmaxf(c0 + c1 + c2, 1.f);
        }
        sInv[t][0] = i0; sInv[t][1] = i1; sInv[t][2] = i2; sInv[t][3] = ia;
        sBias[t] = FIRST ? g_b1[t] : bias_ext[t];
    }

    const __nv_bfloat16* WH = FIRST ? g_W1h : g_W2h;
    const __nv_bfloat16* WL = FIRST ? g_W1l : g_W2l;

    float acc[4][4][4];
    #pragma unroll
    for (int i = 0; i < 4; i++)
        #pragma unroll
        for (int j = 0; j < 4; j++)
            #pragma unroll
            for (int q = 0; q < 4; q++) acc[i][j][q] = 0.f;

    __syncthreads();  // sInv/sBias visible

    // issue cp.async group for chunk c into buffer buf
    auto issue = [&](int c, int buf) {
        // B tiles (always staged)
        uint32_t bd = dynS + OFF_B + buf * 20480;
        const __nv_bfloat16* WHc = WH + c * 32;
        const __nv_bfloat16* WLc = WL + c * 32;
        #pragma unroll
        for (int i = 0; i < 2; i++) {
            int ub = t + i * 256;
            int nr = ub >> 2, j = ub & 3;
            uint32_t dsm = bd + nr * 80 + j * 16;
            const __nv_bfloat16* sh = WHc + (size_t)nr * K + j * 8;
            const __nv_bfloat16* sl = WLc + (size_t)nr * K + j * 8;
            asm volatile("cp.async.cg.shared.global [%0], [%1], 16;" :: "r"(dsm), "l"(sh));
            asm volatile("cp.async.cg.shared.global [%0], [%1], 16;" :: "r"(dsm + 10240), "l"(sl));
        }
        // A stage (raw fp32) — seg3 chunks of GEMM1 are not staged
        bool staged;
        const float* base = feat;
        int colOff = 0;
        if (FIRST) {
            if (c < 12)      { staged = true; base = g_agg + (size_t)(c >> 2) * MAXN * 128; colOff = (c & 3) * 32; }
            else if (c < 16) { staged = false; }
            else             { staged = true; base = feat; colOff = (c - 16) * 32; }
        } else {
            staged = true;
            base = (c < 4) ? g_aggY : g_comb;
            colOff = (c & 3) * 32;
        }
        if (staged) {
            uint32_t sd = dynS + OFF_ST + buf * ST_BYTES;
            #pragma unroll
            for (int i = 0; i < 4; i++) {
                int u2 = t + i * 256;
                int row = u2 >> 3, c4 = (u2 & 7) * 4;
                if (row0 + row < M) {
                    const float* s = base + (size_t)(row0 + row) * 128 + colOff + c4;
                    asm volatile("cp.async.cg.shared.global [%0], [%1], 16;"
                                 :: "r"(sd + (uint32_t)(row * ST_PITCH + c4) * 4), "l"(s));
                }
            }
        }
        asm volatile("cp.async.commit_group;");
    };

    issue(0, 0);

    for (int ci = 0; ci < NC; ci++) {
        int cb = ci & 1, nb = cb ^ 1;
        asm volatile("cp.async.wait_group 0;" ::: "memory");
        __syncthreads();               // chunk ci data visible; prev compute done
        if (ci + 1 < NC) issue(ci + 1, nb);

        // --- convert: stage (or direct LDG for seg3) -> Ah/Al bf16 tiles ----
        const float* stg = (const float*)(dyn + OFF_ST + cb * ST_BYTES);
        #pragma unroll
        for (int i = 0; i < 2; i++) {
            int u = t + i * 256;
            int m = u >> 2, kk8 = (u & 3) * 8;
            int node = row0 + m;
            float v[8];
            #pragma unroll
            for (int j = 0; j < 8; j++) v[j] = 0.f;
            if (node < M) {
                if (FIRST && ci >= 12 && ci < 16) {
                    int kk = (ci - 12) * 32 + kk8;
                    float sc = sInv[m][3];
                    const float4* p0 = (const float4*)(g_agg + (size_t)node * 128 + kk);
                    const float4* p1 = (const float4*)(g_agg + ((size_t)MAXN + node) * 128 + kk);
                    const float4* p2 = (const float4*)(g_agg + ((size_t)2 * MAXN + node) * 128 + kk);
                    float4 a0 = p0[0], b0 = p0[1], a1 = p1[0], b1 = p1[1], a2 = p2[0], b2 = p2[1];
                    v[0] = (a0.x + a1.x + a2.x) * sc; v[1] = (a0.y + a1.y + a2.y) * sc;
                    v[2] = (a0.z + a1.z + a2.z) * sc; v[3] = (a0.w + a1.w + a2.w) * sc;
                    v[4] = (b0.x + b1.x + b2.x) * sc; v[5] = (b0.y + b1.y + b2.y) * sc;
                    v[6] = (b0.z + b1.z + b2.z) * sc; v[7] = (b0.w + b1.w + b2.w) * sc;
                } else {
                    const float* sp = stg + m * ST_PITCH + kk8;
                    float4 a = *(const float4*)sp;
                    float4 b = *(const float4*)(sp + 4);
                    if (FIRST) {
                        if (ci < 12) {
                            float sc = sInv[m][ci >> 2];
                            v[0] = a.x * sc; v[1] = a.y * sc; v[2] = a.z * sc; v[3] = a.w * sc;
                            v[4] = b.x * sc; v[5] = b.y * sc; v[6] = b.z * sc; v[7] = b.w * sc;
                        } else {  // feat
                            v[0] = a.x; v[1] = a.y; v[2] = a.z; v[3] = a.w;
                            v[4] = b.x; v[5] = b.y; v[6] = b.z; v[7] = b.w;
                        }
                    } else {
                        if (ci < 4) {
                            float sc = sInv[m][3];
                            v[0] = a.x * sc; v[1] = a.y * sc; v[2] = a.z * sc; v[3] = a.w * sc;
                            v[4] = b.x * sc; v[5] = b.y * sc; v[6] = b.z * sc; v[7] = b.w * sc;
                        } else {
                            int col = (ci - 4) * 32 + kk8;
                            float4 S0 = *(const float4*)(g_bnS + col);
                            float4 S1 = *(const float4*)(g_bnS + col + 4);
                            float4 B0 = *(const float4*)(g_bnB + col);
                            float4 B1 = *(const float4*)(g_bnB + col + 4);
                            v[0] = a.x * S0.x + B0.x; v[1] = a.y * S0.y + B0.y;
                            v[2] = a.z * S0.z + B0.z; v[3] = a.w * S0.w + B0.w;
                            v[4] = b.x * S1.x + B1.x; v[5] = b.y * S1.y + B1.y;
                            v[6] = b.z * S1.z + B1.z; v[7] = b.w * S1.w + B1.w;
                        }
                    }
                }
            }
            uint32_t hw[4], lw[4];
            #pragma unroll
            for (int p2 = 0; p2 < 4; p2++)
                split_pair(v[2 * p2], v[2 * p2 + 1], hw[p2], lw[p2]);
            *(uint4*)(dyn + OFF_AH + m * 80 + kk8 * 2) = make_uint4(hw[0], hw[1], hw[2], hw[3]);
            *(uint4*)(dyn + OFF_AL + m * 80 + kk8 * 2) = make_uint4(lw[0], lw[1], lw[2], lw[3]);
        }
        __syncthreads();

        // --- compute: 2 k16 steps, warp owns 64x32 of the 128x128 tile ------
        uint32_t* Bh32 = (uint32_t*)(dyn + OFF_B + cb * 20480);
        uint32_t* Bl32 = Bh32 + 2560;
        #pragma unroll
        for (int ks = 0; ks < 2; ks++) {
            int kw = ks * 8 + tig;
            uint32_t bh[4][2], bl[4][2];
            #pragma unroll
            for (int nA = 0; nA < 4; nA++) {
                int cN = warpN * 32 + nA * 8 + g;
                bh[nA][0] = Bh32[cN * AP_W + kw];
                bh[nA][1] = Bh32[cN * AP_W + kw + 4];
                bl[nA][0] = Bl32[cN * AP_W + kw];
                bl[nA][1] = Bl32[cN * AP_W + kw + 4];
            }
            #pragma unroll
            for (int mA = 0; mA < 4; mA++) {
                int r0 = warpM * 64 + mA * 16 + g;
                uint32_t ah[4], al[4];
                ah[0] = Ah32[r0 * AP_W + kw];
                ah[1] = Ah32[(r0 + 8) * AP_W + kw];
                ah[2] = Ah32[r0 * AP_W + kw + 4];
                ah[3] = Ah32[(r0 + 8) * AP_W + kw + 4];
                al[0] = Al32[r0 * AP_W + kw];
                al[1] = Al32[(r0 + 8) * AP_W + kw];
                al[2] = Al32[r0 * AP_W + kw + 4];
                al[3] = Al32[(r0 + 8) * AP_W + kw + 4];
                #pragma unroll
                for (int nA = 0; nA < 4; nA++) {
                    mma16816(acc[mA][nA], ah, bh[nA]);
                    mma16816(acc[mA][nA], ah, bl[nA]);
                    mma16816(acc[mA][nA], al, bh[nA]);
                }
            }
        }
    }
    __syncthreads();   // all compute done before smem reuse in epilogue

    // --- epilogue: bias (+ReLU), stores; FIRST also accumulates BN stats ----
    float* Cp = FIRST ? g_comb : Cext;
    float* sS = (float*)dyn;
    float* sQ = sS + 128;
    if (FIRST) {
        if (t < 128) { sS[t] = 0.f; sQ[t] = 0.f; }
        __syncthreads();
    }

    #pragma unroll
    for (int nA = 0; nA < 4; nA++) {
        int col = warpN * 32 + nA * 8 + 2 * tig;
        float s0 = 0.f, s1 = 0.f, q0 = 0.f, q1 = 0.f;
        #pragma unroll
        for (int mA = 0; mA < 4; mA++) {
            #pragma unroll
            for (int half = 0; half < 2; half++) {
                int row = row0 + warpM * 64 + mA * 16 + g + half * 8;
                if (row < M) {
                    float v0 = acc[mA][nA][half * 2 + 0] + sBias[col];
                    float v1 = acc[mA][nA][half * 2 + 1] + sBias[col + 1];
                    if (FIRST) { v0 = fmaxf(v0, 0.f); v1 = fmaxf(v1, 0.f); }
                    *(float2*)&Cp[(size_t)row * 128 + col] = make_float2(v0, v1);
                    if (FIRST) {
                        s0 += v0; s1 += v1;
                        q0 += v0 * v0; q1 += v1 * v1;
                    }
                }
            }
        }
        if (FIRST) {
            atomicAdd(&sS[col], s0); atomicAdd(&sS[col + 1], s1);
            atomicAdd(&sQ[col], q0); atomicAdd(&sQ[col + 1], q1);
        }
    }
    if (FIRST) {
        __syncthreads();
        if (t < 128) {
            atomicAdd(&g_stats[t], sS[t]);
            atomicAdd(&g_stats[128 + t], sQ[t]);
        }
    }
}

// ---------------- host launcher ----------------------------------------------
extern "C" void kernel_launch(void* const* d_in, const int* in_sizes, int n_in,
                              void* d_out, int out_size) {
    const float* feat = nullptr;
    const int* ei[3] = {nullptr, nullptr, nullptr};
    int ne[3] = {0, 0, 0};
    const float* Wm[10] = {};
    const float* vec[7] = {};
    const float* wt = nullptr;
    int ke = 0, km = 0, kv = 0, n = 0;

    for (int i = 0; i < n_in; i++) {
        int sz = in_sizes[i];
        if (sz == 3) { wt = (const float*)d_in[i]; }
        else if (sz == D) { if (kv < 7) vec[kv++] = (const float*)d_in[i]; }
        else if (sz == D * D) { if (km < 10) Wm[km++] = (const float*)d_in[i]; }
        else if (sz == 2 * MAXE) { if (ke < 3) { ei[ke] = (const int*)d_in[i]; ne[ke] = sz / 2; ke++; } }
        else if (sz == MAXN * D) { feat = (const float*)d_in[i]; n = sz / D; }
    }
    if (!feat || ke != 3 || km != 10 || kv != 7 || !wt) return;

    const float* Wl0 = Wm[0], *Wr0 = Wm[1], *Wl1 = Wm[2], *Wr1 = Wm[3];
    const float* Wl2 = Wm[4], *Wr2 = Wm[5], *Wla = Wm[6], *Wra = Wm[7];
    const float* Wf  = Wm[8], *Wrf = Wm[9];
    const float* bl0 = vec[0], *bl1 = vec[1], *bl2 = vec[2], *bla = vec[3];
    const float* bf  = vec[4], *gamma = vec[5], *beta = vec[6];

    const int T = 256;
    cudaFuncSetAttribute(gemm_hmma<640, true>,
                         cudaFuncAttributeMaxDynamicSharedMemorySize, SMEM_TOT);
    cudaFuncSetAttribute(gemm_hmma<256, false>,
                         cudaFuncAttributeMaxDynamicSharedMemorySize, SMEM_TOT);

    int neMax = ne[0] > ne[1] ? ne[0] : ne[1];
    if (ne[2] > neMax) neMax = ne[2];
    int edgesPerBlock = (T / 32) * EPW;   // 64
    int bPer = (neMax + edgesPerBlock - 1) / edgesPerBlock;

    // 1) zero scratch
    {
        size_t tot = (size_t)3 * MAXN * 32 + (size_t)MAXN * 32 + (3 * MAXN) / 4 + 64;
        zero_bufs<<<(unsigned)((tot + T - 1) / T), T>>>();
    }
    // 2) phase-1 scatter (all 3 types in one launch)
    scatter3<0><<<3 * bPer, T>>>((const float4*)feat,
                                 ei[0], ei[0] + ne[0], ei[1], ei[1] + ne[1],
                                 ei[2], ei[2] + ne[2], ne[0], ne[1], ne[2], bPer);
    // 3) fold weights + bf16 split
    prep_weights<<<(128 * 640 + T - 1) / T, T>>>(Wl0, Wr0, Wl1, Wr1, Wl2, Wr2,
                                                 Wla, Wra, Wf, Wrf,
                                                 bl0, bl1, bl2, bla, wt);
    // 4) GEMM1 (pipelined HMMA bf16x3, fused mean + bias + relu + BN-stats)
    {
        int blocks = (n + 127) / 128;
        gemm_hmma<640, true><<<blocks, 256, SMEM_TOT>>>(feat, nullptr, nullptr, n);
    }
    // 5) BN finalize (scale/shift)
    bn_finalize<<<1, 128>>>(gamma, beta, n);
    // 6) phase-2 scatter (source = g_comb selected device-side, BN on read)
    scatter3<1><<<3 * bPer, T>>>((const float4*)feat,
                                 ei[0], ei[0] + ne[0], ei[1], ei[1] + ne[1],
                                 ei[2], ei[2] + ne[2], ne[0], ne[1], ne[2], bPer);
    // 7) GEMM2 (pipelined HMMA bf16x3, fused mean + BN + bias) -> d_out
    {
        int blocks = (n + 127) / 128;
        gemm_hmma<256, false><<<blocks, 256, SMEM_TOT>>>(feat, bf, (float*)d_out, n);
    }
    (void)out_size;
}